// round 6
// baseline (speedup 1.0000x reference)
#include <cuda_runtime.h>
#include <math.h>

typedef unsigned long long ull;

#define BATCH  1024
#define TSTEPS 1024
#define DIN    6
#define UNITS  64
#define WIDTH  128
#define DOUT   6
#define K0     70
#define EPSF   1e-8f
#define ROWS   8
#define NTH    256
#define NBLK   (BATCH / ROWS)

// ---------------- shared memory layout (float offsets) ----------------
// Weights: col-major, ODD stride (conflict-free LDS.32): W[j*stride + k]
// Acts: plain rowmajor-by-k: k*8 + r  (8 rows)
// STGO: L2 x1/x2 exchange m*1024 + p*256 + j*2 + e
//       then head partials  g*512 + p*128 + jh*2 + e
#define W10O  0                    // 128*71
#define W20O  9088
#define W11O  18176                // 128*129
#define W21O  34688
#define WOUTO 51200                // 384
#define BA    51584
#define BB    51648
#define C0P   51712                // 70*8 = 560   [x(6) | h(64)] plain
#define CBD   52272                // 128*8 = 1024
#define CB2   53296                // 1024
#define STGO  54320                // 2048
#define XB    56368                // 48
#define NB    56416                // 8
#define SMF   56424                // 225,696 bytes

__device__ __forceinline__ ull pack2(float lo, float hi) {
    ull r; asm("mov.b64 %0, {%1, %2};" : "=l"(r) : "f"(lo), "f"(hi)); return r;
}
__device__ __forceinline__ void unpack2(ull v, float& lo, float& hi) {
    asm("mov.b64 {%0, %1}, %2;" : "=f"(lo), "=f"(hi) : "l"(v));
}
__device__ __forceinline__ void ffma2(ull& d, ull a, ull b) {
    asm("fma.rn.f32x2 %0, %1, %2, %0;" : "+l"(d) : "l"(a), "l"(b));
}

// Fused both-mats layer. Acc packs (mat1,mat2) per row. Acts plain (1 bcast LDS.128/k),
// weights two conflict-free LDS.32/k. g[i] = tanh(x1)*tanh(x2), 4 rows.
template<int K, int UNR>
__device__ __forceinline__ void layer_fused(float (&g)[4], const float* __restrict__ actp,
                                            const float* __restrict__ wp1,
                                            const float* __restrict__ wp2, ull binit)
{
    ull a0 = binit, a1 = binit, a2 = binit, a3 = binit;
#pragma unroll UNR
    for (int k = 0; k < K; k++) {
        const float4 q = *(const float4*)(actp + k * 8);
        const ull w = pack2(wp1[k], wp2[k]);
        ffma2(a0, pack2(q.x, q.x), w);
        ffma2(a1, pack2(q.y, q.y), w);
        ffma2(a2, pack2(q.z, q.z), w);
        ffma2(a3, pack2(q.w, q.w), w);
    }
    float x1, x2;
    unpack2(a0, x1, x2); g[0] = tanhf(x1) * tanhf(x2);
    unpack2(a1, x1, x2); g[1] = tanhf(x1) * tanhf(x2);
    unpack2(a2, x1, x2); g[2] = tanhf(x1) * tanhf(x2);
    unpack2(a3, x1, x2); g[3] = tanhf(x1) * tanhf(x2);
}

__global__ void __launch_bounds__(NTH, 1)
lmsc_kernel(const float* __restrict__ x,   const float* __restrict__ initF,
            const float* __restrict__ w10, const float* __restrict__ b10,
            const float* __restrict__ w20, const float* __restrict__ b20,
            const float* __restrict__ w11, const float* __restrict__ b11,
            const float* __restrict__ w21, const float* __restrict__ b21,
            const float* __restrict__ w12, const float* __restrict__ b12,
            const float* __restrict__ w22, const float* __restrict__ b22,
            const float* __restrict__ wa,  const float* __restrict__ ba,
            const float* __restrict__ wb,  const float* __restrict__ bb,
            const float* __restrict__ wout, float* __restrict__ out)
{
    extern __shared__ float sm[];
    const int tid = threadIdx.x;
    const int b0  = blockIdx.x * ROWS;
    const int rh  = tid >> 7;        // row-half for fused layers; mat index for L2
    const int j   = tid & 127;       // column

    // ---- SMEM weight init (col-major, odd stride) ----
    for (int idx = tid; idx < K0 * WIDTH; idx += NTH) {
        int k = idx >> 7, jj = idx & 127;
        sm[W10O + jj * 71 + k] = w10[idx];
        sm[W20O + jj * 71 + k] = w20[idx];
    }
    for (int idx = tid; idx < WIDTH * WIDTH; idx += NTH) {
        int k = idx >> 7, jj = idx & 127;
        sm[W11O + jj * 129 + k] = w11[idx];
        sm[W21O + jj * 129 + k] = w21[idx];
    }
    for (int idx = tid; idx < UNITS * DOUT; idx += NTH) sm[WOUTO + idx] = wout[idx];
    if (tid < 64) { sm[BA + tid] = ba[tid]; sm[BB + tid] = bb[tid]; }
    // h0 plain
    for (int idx = tid; idx < ROWS * UNITS; idx += NTH) {
        int r = idx >> 6, jj = idx & 63;
        sm[C0P + (6 + jj) * 8 + r] = initF[(b0 + r) * (2 + UNITS) + 2 + jj];
    }

    // ---- per-thread register state ----
    const ull bp0 = pack2(b10[j], b20[j]);
    const ull bp1 = pack2(b11[j], b21[j]);
    const float bias2 = (rh ? b22 : b12)[j];

    float wl2[128];
    {
        const float* wsrc = rh ? w22 : w12;
#pragma unroll
        for (int k = 0; k < 128; k++) wl2[k] = wsrc[k * 128 + j];
    }
    const int hm = tid >> 7;
    const int kh = (tid >> 6) & 1;
    const int jh = tid & 63;
    float whd[64];
    {
        const float* hsrc = hm ? wb : wa;
#pragma unroll
        for (int i = 0; i < 64; i++) whd[i] = hsrc[(kh * 64 + i) * 64 + jh];
    }

    const float* actC0 = sm + C0P + rh * 4;
    const float* actCB = sm + CBD + rh * 4;
    const float* wp10  = sm + W10O + j * 71;
    const float* wp20  = sm + W20O + j * 71;
    const float* wp11  = sm + W11O + j * 129;
    const float* wp21  = sm + W21O + j * 129;

    // ---- x prologue: stage x(0), compute norm, prefetch x(1) ----
    const int xr = tid / 6, xd = tid - 6 * xr;
    float xc = 0.f;
    if (tid < 48) sm[XB + tid] = x[((size_t)(b0 + xr) * TSTEPS) * 6 + xd];
    __syncthreads();
    if (tid < 8) {
        float s = 0.f;
#pragma unroll
        for (int d = 0; d < 6; d++) { float v = sm[XB + tid * 6 + d]; s = fmaf(v, v, s); }
        float nrm = sqrtf(s);
        sm[NB + tid] = nrm;
        float inv = 1.0f / (nrm + EPSF);
#pragma unroll
        for (int d = 0; d < 6; d++) sm[C0P + d * 8 + tid] = sm[XB + tid * 6 + d] * inv;
    }
    if (tid < 48) xc = x[((size_t)(b0 + xr) * TSTEPS + 1) * 6 + xd];

    float* outs = out;
    float* alph = out + (size_t)BATCH * TSTEPS * DOUT;

#pragma unroll 1
    for (int t = 0; t < TSTEPS; t++) {
        __syncthreads();                                   // A: x/h/norm ready

        {   // layer 0 fused -> CBD (plain)
            float g[4];
            layer_fused<K0, 14>(g, actC0, wp10, wp20, bp0);
            *(float4*)(sm + CBD + j * 8 + rh * 4) = make_float4(g[0], g[1], g[2], g[3]);
        }
        __syncthreads();                                   // B

        {   // layer 1 fused -> CB2 (plain)
            float g[4];
            layer_fused<WIDTH, 16>(g, actCB, wp11, wp21, bp1);
            *(float4*)(sm + CB2 + j * 8 + rh * 4) = make_float4(g[0], g[1], g[2], g[3]);
        }
        __syncthreads();                                   // C

        {   // layer 2: split-mat, reg weights, rowpair acc -> STGO (m*1024 + p*256 + j*2)
            ull bp = pack2(bias2, bias2);
            ull a0 = bp, a1 = bp, a2 = bp, a3 = bp;
#pragma unroll
            for (int k = 0; k < 128; k++) {
                ulonglong2 u0 = *(const ulonglong2*)(sm + CB2 + k * 8);
                ulonglong2 u1 = *(const ulonglong2*)(sm + CB2 + k * 8 + 4);
                ull w = pack2(wl2[k], wl2[k]);
                ffma2(a0, u0.x, w); ffma2(a1, u0.y, w);
                ffma2(a2, u1.x, w); ffma2(a3, u1.y, w);
            }
            *(ull*)(sm + STGO + rh * 1024 + 0 * 256 + j * 2) = a0;
            *(ull*)(sm + STGO + rh * 1024 + 1 * 256 + j * 2) = a1;
            *(ull*)(sm + STGO + rh * 1024 + 2 * 256 + j * 2) = a2;
            *(ull*)(sm + STGO + rh * 1024 + 3 * 256 + j * 2) = a3;
        }
        __syncthreads();                                   // D

        // gate pass: CB2[j'*8 + p*2 + e] = tanh(x1 * x2)
#pragma unroll
        for (int it = 0; it < 4; it++) {
            int idx = it * 256 + tid;
            int jq  = idx >> 3;
            int rem = idx & 7;
            int src = ((rem >> 1) * 256) + jq * 2 + (rem & 1);
            float x1 = sm[STGO + src];
            float x2 = sm[STGO + 1024 + src];
            sm[CB2 + idx] = tanhf(x1 * x2);
        }
        __syncthreads();                                   // E

        {   // heads: split-K, reg weights -> compact partials g*512 + p*128 + jh*2 + e
            const float* actH = sm + CB2 + kh * 512;
            ull a0 = 0, a1 = 0, a2 = 0, a3 = 0;
#pragma unroll
            for (int i = 0; i < 64; i++) {
                ulonglong2 u0 = *(const ulonglong2*)(actH + i * 8);
                ulonglong2 u1 = *(const ulonglong2*)(actH + i * 8 + 4);
                ull w = pack2(whd[i], whd[i]);
                ffma2(a0, u0.x, w); ffma2(a1, u0.y, w);
                ffma2(a2, u1.x, w); ffma2(a3, u1.y, w);
            }
            const int g = hm * 2 + kh;
            *(ull*)(sm + STGO + g * 512 + 0 * 128 + jh * 2) = a0;
            *(ull*)(sm + STGO + g * 512 + 1 * 128 + jh * 2) = a1;
            *(ull*)(sm + STGO + g * 512 + 2 * 128 + jh * 2) = a2;
            *(ull*)(sm + STGO + g * 512 + 3 * 128 + jh * 2) = a3;
        }
        __syncthreads();                                   // F

        {   // combine: alpha/beta, h update, alpha out; also stage x(t+1)
            const int jj = tid & 63;
            const int rg = tid >> 6;
#pragma unroll
            for (int rr = 0; rr < 2; rr++) {
                const int r = rg * 2 + rr;
                float pa = sm[STGO + 0 * 512 + rg * 128 + jj * 2 + rr]
                         + sm[STGO + 1 * 512 + rg * 128 + jj * 2 + rr];
                float pb = sm[STGO + 2 * 512 + rg * 128 + jj * 2 + rr]
                         + sm[STGO + 3 * 512 + rg * 128 + jj * 2 + rr];
                float alpha = expf(pa + sm[BA + jj]);
                float beta  = tanhf(pb + sm[BB + jj]);
                float hold  = sm[C0P + (6 + jj) * 8 + r];
                float hn = fmaf(expf(-alpha * sm[NB + r]), hold - beta, beta);
                sm[C0P + (6 + jj) * 8 + r] = hn;
                alph[((size_t)(b0 + r) * TSTEPS + t) * 64 + jj] = alpha;
            }
            if (tid < 48 && t + 1 < TSTEPS) sm[XB + tid] = xc;
        }
        __syncthreads();                                   // G: h_new + x(t+1) staged

        if (tid < 48) {   // outs = h_new @ wout; also prefetch x(t+2)
            const int r = tid / 6, o = tid - 6 * r;
            float acc = 0.f;
#pragma unroll
            for (int k = 0; k < 64; k++)
                acc = fmaf(sm[C0P + (6 + k) * 8 + r], sm[WOUTO + k * 6 + o], acc);
            outs[((size_t)(b0 + r) * TSTEPS + t) * 6 + o] = acc;
            if (t + 2 < TSTEPS)
                xc = x[((size_t)(b0 + xr) * TSTEPS + (t + 2)) * 6 + xd];
        }
        if (tid < 8) {    // norm + xn for step t+1
            float s = 0.f;
#pragma unroll
            for (int d = 0; d < 6; d++) { float v = sm[XB + tid * 6 + d]; s = fmaf(v, v, s); }
            float nrm = sqrtf(s);
            sm[NB + tid] = nrm;
            float inv = 1.0f / (nrm + EPSF);
#pragma unroll
            for (int d = 0; d < 6; d++) sm[C0P + d * 8 + tid] = sm[XB + tid * 6 + d] * inv;
        }
    }
}

extern "C" void kernel_launch(void* const* d_in, const int* in_sizes, int n_in,
                              void* d_out, int out_size)
{
    const float* x     = (const float*)d_in[0];
    const float* initF = (const float*)d_in[1];
    const float* w10   = (const float*)d_in[2];
    const float* b10   = (const float*)d_in[3];
    const float* w20   = (const float*)d_in[4];
    const float* b20   = (const float*)d_in[5];
    const float* w11   = (const float*)d_in[6];
    const float* b11   = (const float*)d_in[7];
    const float* w21   = (const float*)d_in[8];
    const float* b21   = (const float*)d_in[9];
    const float* w12   = (const float*)d_in[10];
    const float* b12   = (const float*)d_in[11];
    const float* w22   = (const float*)d_in[12];
    const float* b22   = (const float*)d_in[13];
    const float* wa    = (const float*)d_in[14];
    const float* ba    = (const float*)d_in[15];
    const float* wb    = (const float*)d_in[16];
    const float* bb    = (const float*)d_in[17];
    const float* wout  = (const float*)d_in[18];
    float* out = (float*)d_out;

    const int smem_bytes = SMF * 4;
    cudaFuncSetAttribute(lmsc_kernel, cudaFuncAttributeMaxDynamicSharedMemorySize, smem_bytes);

    lmsc_kernel<<<NBLK, NTH, smem_bytes>>>(x, initF,
                                           w10, b10, w20, b20,
                                           w11, b11, w21, b21,
                                           w12, b12, w22, b22,
                                           wa, ba, wb, bb, wout, out);
}